// round 15
// baseline (speedup 1.0000x reference)
#include <cuda_runtime.h>
#include <cuda_fp16.h>
#include <cstdint>

#define ULL unsigned long long

// ---------------- global scratch (no allocation) ----------------
__device__ float g_ha[512 * 768];
__device__ float g_hb[512 * 768];
__device__ __half g_xh[2][512 * 768];
__device__ __half g_wh[2][768 * 768];   // [k][n], natural layout

__device__ __forceinline__ ULL fma2(ULL a, ULL b, ULL c) {
    ULL d;
    asm("fma.rn.f32x2 %0, %1, %2, %3;" : "=l"(d) : "l"(a), "l"(b), "l"(c));
    return d;
}
__device__ __forceinline__ ULL add2(ULL a, ULL b) {
    ULL d;
    asm("add.rn.f32x2 %0, %1, %2;" : "=l"(d) : "l"(a), "l"(b));
    return d;
}
union F2U { ULL u; float2 f; };
union F4U { float4 f; ULL u[2]; float s[4]; uint4 q; };
union H4U { __half2 h2[2]; uint2 q; };

__device__ __forceinline__ uint32_t s2u(const void* p) {
    uint32_t a;
    asm("{ .reg .u64 t; cvta.to.shared.u64 t, %1; cvt.u32.u64 %0, t; }" : "=r"(a) : "l"(p));
    return a;
}
__device__ __forceinline__ void cpa16(const void* smem_dst, const void* gsrc) {
    uint32_t d = s2u(smem_dst);
    asm volatile("cp.async.ca.shared.global [%0], [%1], 16;" :: "r"(d), "l"(gsrc) : "memory");
}
__device__ __forceinline__ void redadd2(float* p, float v0, float v1) {
    asm volatile("red.global.add.v2.f32 [%0], {%1, %2};"
                 :: "l"(p), "f"(v0), "f"(v1) : "memory");
}
#define CP_COMMIT() asm volatile("cp.async.commit_group;" ::: "memory")
#define CP_WAIT2()  asm volatile("cp.async.wait_group 2;" ::: "memory")

#define LDSM4(r, addr)                                                         \
    asm volatile("ldmatrix.sync.aligned.m8n8.x4.shared.b16 {%0,%1,%2,%3}, [%4];" \
                 : "=r"((r)[0]), "=r"((r)[1]), "=r"((r)[2]), "=r"((r)[3])      \
                 : "r"(addr))
#define LDSM4T(r, addr)                                                        \
    asm volatile("ldmatrix.sync.aligned.m8n8.x4.trans.shared.b16 {%0,%1,%2,%3}, [%4];" \
                 : "=r"((r)[0]), "=r"((r)[1]), "=r"((r)[2]), "=r"((r)[3])      \
                 : "r"(addr))
#define MMA16816(c, a, b)                                                      \
    asm volatile("mma.sync.aligned.m16n8k16.row.col.f32.f16.f16.f32 "          \
                 "{%0,%1,%2,%3},{%4,%5,%6,%7},{%8,%9},{%0,%1,%2,%3};"          \
                 : "+f"((c)[0]), "+f"((c)[1]), "+f"((c)[2]), "+f"((c)[3])      \
                 : "r"((a)[0]), "r"((a)[1]), "r"((a)[2]), "r"((a)[3]),         \
                   "r"((b)[0]), "r"((b)[1]))

// ---------------------------------------------------------------------------
// cvt: fp32 -> fp16 for X (a,b) and W1, plus out-init to b2.  MLP=4:
// each thread owns 4 consecutive float4 units; loads front-batched.
//   [0,192):   X  (196608 units; z-boundary exact at block 96)
//   [192,480): W  (294912 units; z-boundary exact at block 144)
//   [480,512): out-init (32768 units)
// ---------------------------------------------------------------------------
__global__ __launch_bounds__(256) void cvt_kernel(
    const float* __restrict__ A, const float* __restrict__ Bx,
    const float* __restrict__ W1, const float* __restrict__ b2,
    float* __restrict__ out)
{
    const int bid = blockIdx.x;
    const int tid = threadIdx.x;

    if (bid < 192) {
        const int gid = bid * 256 + tid;            // 0..49151
        const int z   = gid / 24576;
        const int r0  = (gid - z * 24576) * 4;      // float4 unit index
        const float* src = (z ? Bx : A) + r0 * 4;
        float4 v[4];
#pragma unroll
        for (int j = 0; j < 4; j++) v[j] = *(const float4*)(src + 4 * j);
        H4U h[4];
#pragma unroll
        for (int j = 0; j < 4; j++) {
            h[j].h2[0] = __float22half2_rn(make_float2(v[j].x, v[j].y));
            h[j].h2[1] = __float22half2_rn(make_float2(v[j].z, v[j].w));
        }
        uint4 q0, q1;
        q0.x = h[0].q.x; q0.y = h[0].q.y; q0.z = h[1].q.x; q0.w = h[1].q.y;
        q1.x = h[2].q.x; q1.y = h[2].q.y; q1.z = h[3].q.x; q1.w = h[3].q.y;
        *(uint4*)&g_xh[z][r0 * 4]     = q0;
        *(uint4*)&g_xh[z][r0 * 4 + 8] = q1;
    } else if (bid < 480) {
        const int gid = (bid - 192) * 256 + tid;    // 0..73727
        const int z   = gid / 36864;
        const int r0  = (gid - z * 36864) * 4;
        const float* src = W1 + z * 589824 + r0 * 4;
        float4 v[4];
#pragma unroll
        for (int j = 0; j < 4; j++) v[j] = *(const float4*)(src + 4 * j);
        H4U h[4];
#pragma unroll
        for (int j = 0; j < 4; j++) {
            h[j].h2[0] = __float22half2_rn(make_float2(v[j].x, v[j].y));
            h[j].h2[1] = __float22half2_rn(make_float2(v[j].z, v[j].w));
        }
        uint4 q0, q1;
        q0.x = h[0].q.x; q0.y = h[0].q.y; q0.z = h[1].q.x; q0.w = h[1].q.y;
        q1.x = h[2].q.x; q1.y = h[2].q.y; q1.z = h[3].q.x; q1.w = h[3].q.y;
        *(uint4*)&g_wh[z][r0 * 4]     = q0;
        *(uint4*)&g_wh[z][r0 * 4 + 8] = q1;
    } else {
        const int gid = (bid - 480) * 256 + tid;    // 0..8191, 16 floats each
        const float b0 = b2[0], b1v = b2[1];
        const float4 r = make_float4(b0, b1v, b0, b1v);
#pragma unroll
        for (int j = 0; j < 4; j++) *(float4*)&out[gid * 16 + 4 * j] = r;
    }
}

// ---------------------------------------------------------------------------
// gemm (R12 verbatim): fp16 warp-MMA GEMM.  D = X@W (+b1 if z==0), fp32 accum.
// BM=64, BN=64, BK=32, 24 chunks, 4-stage cp.async.
// Grid (8 m, 12 n, 2 z) = 192 CTAs, 256 thr (8 warps: 4m x 2n).
// ---------------------------------------------------------------------------
__global__ __launch_bounds__(256) void gemm_kernel(const float* __restrict__ b1)
{
    const int z  = blockIdx.z;
    const int m0 = blockIdx.x * 64;
    const int n0 = blockIdx.y * 64;

    __shared__ __half As[4][64][40];
    __shared__ __half Bs[4][32][72];

    const int tid  = threadIdx.x;
    const int lane = tid & 31;
    const int wid  = tid >> 5;
    const int wm   = wid & 3;
    const int wn   = wid >> 2;

    const __half* __restrict__ xs = g_xh[z];
    const __half* __restrict__ ws = g_wh[z];

    float acc[4][4];
#pragma unroll
    for (int in = 0; in < 4; in++)
#pragma unroll
        for (int r = 0; r < 4; r++) acc[in][r] = 0.f;

    const int arow = (lane & 7) + 8 * ((lane >> 3) & 1);
    const int akh  = ((lane >> 4) & 1) * 8;
    const int bk   = (lane & 7) + 8 * ((lane >> 3) & 1);
    const int bn8  = ((lane >> 4) & 1) * 8;

    const int amr = tid >> 2, aq = tid & 3;
    const int bkr = tid >> 3, bq = tid & 7;

    auto issue = [&](int c, int s) {
        const int k0 = c * 32;
        cpa16(&As[s][amr][aq * 8], &xs[(m0 + amr) * 768 + k0 + aq * 8]);
        cpa16(&Bs[s][bkr][bq * 8], &ws[(k0 + bkr) * 768 + n0 + bq * 8]);
    };

    issue(0, 0); CP_COMMIT();
    issue(1, 1); CP_COMMIT();
    issue(2, 2); CP_COMMIT();

    for (int c = 0; c < 24; c++) {
        const int s = c & 3;
        CP_WAIT2();
        __syncthreads();

        if (c + 3 < 24) issue(c + 3, (c + 3) & 3);
        CP_COMMIT();

#pragma unroll
        for (int kk = 0; kk < 2; kk++) {
            uint32_t a_[4], b0_[4], b1_[4];
            LDSM4(a_, s2u(&As[s][wm * 16 + arow][kk * 16 + akh]));
            LDSM4T(b0_, s2u(&Bs[s][kk * 16 + bk][wn * 32 + 0  + bn8]));
            LDSM4T(b1_, s2u(&Bs[s][kk * 16 + bk][wn * 32 + 16 + bn8]));
            MMA16816(acc[0], a_, &b0_[0]);
            MMA16816(acc[1], a_, &b0_[2]);
            MMA16816(acc[2], a_, &b1_[0]);
            MMA16816(acc[3], a_, &b1_[2]);
        }
    }

    float* __restrict__ outp = z ? g_hb : g_ha;
#pragma unroll
    for (int in = 0; in < 4; in++) {
        const int mA = m0 + wm * 16 + (lane >> 2);
        const int nG = n0 + wn * 32 + in * 8 + 2 * (lane & 3);
        float2 v0 = make_float2(acc[in][0], acc[in][1]);
        float2 v1 = make_float2(acc[in][2], acc[in][3]);
        if (z == 0) {
            float2 bb = *(const float2*)&b1[nG];
            v0.x += bb.x; v0.y += bb.y;
            v1.x += bb.x; v1.y += bb.y;
        }
        *(float2*)&outp[mA * 768 + nG]       = v0;
        *(float2*)&outp[(mA + 8) * 768 + nG] = v1;
    }
}

// ---------------------------------------------------------------------------
// pair_kernel v3: 4 s per warp, h-SPLIT x8, SINGLE chunk of 96 h.
// 1024 blocks x 4 warps = 27.7 warps/SM (2x R14 occupancy); load latency
// hidden by cross-block overlap instead of intra-block double buffering.
// Grid (4 b, 8 s-tiles of 16, 32 = hs*4 + ttile).
// Partials REDG'd (v2) onto out (pre-initialized to b2 by cvt).
// ---------------------------------------------------------------------------
__global__ __launch_bounds__(128) void pair_kernel(
    const float* __restrict__ W2, float* __restrict__ out)
{
    const int b  = blockIdx.x;
    const int s0 = blockIdx.y * 16;
    const int t0 = (blockIdx.z & 3) * 32;
    const int h0 = (blockIdx.z >> 2) * 96;

    __shared__ __align__(16) float4 haS[4][2][48];  // [w][s-pair][hp]
    __shared__ ULL hbT[48][33];                     // [hp][t]
    __shared__ __align__(16) float4 wsS[48];        // (w0h,w0h',w1h,w1h')

    const int tid  = threadIdx.x;
    const int w    = tid >> 5;
    const int lane = tid & 31;

    // ha staging: 384 units; unit q -> (ww=q/96, p=(q%96)/48, hp=q%48)
    unsigned aw[3], ap[3], ah[3];
#pragma unroll
    for (int i = 0; i < 3; i++) {
        unsigned q = (unsigned)tid + 128u * i;
        aw[i] = q / 96u;
        unsigned rem = q % 96u;
        ap[i] = rem / 48u;
        ah[i] = rem % 48u;
    }
    // hb staging: 768 float4 units; q -> (t=q/24, cq=q%24)
    unsigned tq[6], hq[6];
#pragma unroll
    for (int i = 0; i < 6; i++) {
        unsigned q = (unsigned)tid + 128u * i;
        tq[i] = q / 24u; hq[i] = q % 24u;
    }

    // ---- load + stage (front-batched loads for MLP) ----
    float2 pa0[3], pa1[3];
    float4 pb[6];
    float4 pw;
#pragma unroll
    for (int i = 0; i < 3; i++) {
        int sa = b * 128 + s0 + 4 * aw[i] + 2 * ap[i];
        pa0[i] = *(const float2*)&g_ha[sa * 768 + h0 + 2 * ah[i]];
        pa1[i] = *(const float2*)&g_ha[(sa + 1) * 768 + h0 + 2 * ah[i]];
    }
#pragma unroll
    for (int i = 0; i < 6; i++)
        pb[i] = *(const float4*)&g_hb[(b * 128 + t0 + tq[i]) * 768 + h0 + hq[i] * 4];
    if (tid < 48) pw = *(const float4*)&W2[(h0 + 2 * tid) * 2];

#pragma unroll
    for (int i = 0; i < 3; i++)
        haS[aw[i]][ap[i]][ah[i]] = make_float4(pa0[i].x, pa0[i].y, pa1[i].x, pa1[i].y);
#pragma unroll
    for (int i = 0; i < 6; i++) {
        F2U d0; d0.f.x = pb[i].x; d0.f.y = pb[i].y;
        F2U d1; d1.f.x = pb[i].z; d1.f.y = pb[i].w;
        hbT[2 * hq[i] + 0][tq[i]] = d0.u;
        hbT[2 * hq[i] + 1][tq[i]] = d1.u;
    }
    if (tid < 48) wsS[tid] = make_float4(pw.x, pw.z, pw.y, pw.w);
    __syncthreads();

    ULL acc[4][2];
#pragma unroll
    for (int i = 0; i < 4; i++) { acc[i][0] = 0ull; acc[i][1] = 0ull; }

#pragma unroll 8
    for (int hp = 0; hp < 48; hp++) {
        F4U a0; a0.f = haS[w][0][hp];
        F4U a1; a1.f = haS[w][1][hp];
        ULL vb = hbT[hp][lane];
        F4U wv; wv.f = wsS[hp];

        F2U x00; x00.u = add2(a0.u[0], vb);
        x00.f.x = fmaxf(x00.f.x, 0.f); x00.f.y = fmaxf(x00.f.y, 0.f);
        F2U x01; x01.u = add2(a0.u[1], vb);
        x01.f.x = fmaxf(x01.f.x, 0.f); x01.f.y = fmaxf(x01.f.y, 0.f);
        F2U x10; x10.u = add2(a1.u[0], vb);
        x10.f.x = fmaxf(x10.f.x, 0.f); x10.f.y = fmaxf(x10.f.y, 0.f);
        F2U x11; x11.u = add2(a1.u[1], vb);
        x11.f.x = fmaxf(x11.f.x, 0.f); x11.f.y = fmaxf(x11.f.y, 0.f);

        acc[0][0] = fma2(x00.u, wv.u[0], acc[0][0]);
        acc[0][1] = fma2(x00.u, wv.u[1], acc[0][1]);
        acc[1][0] = fma2(x01.u, wv.u[0], acc[1][0]);
        acc[1][1] = fma2(x01.u, wv.u[1], acc[1][1]);
        acc[2][0] = fma2(x10.u, wv.u[0], acc[2][0]);
        acc[2][1] = fma2(x10.u, wv.u[1], acc[2][1]);
        acc[3][0] = fma2(x11.u, wv.u[0], acc[3][0]);
        acc[3][1] = fma2(x11.u, wv.u[1], acc[3][1]);
    }

    const int t = t0 + lane;
#pragma unroll
    for (int i = 0; i < 4; i++) {
        const int s = s0 + 4 * w + i;
        F2U r0, r1;
        r0.u = acc[i][0]; r1.u = acc[i][1];
        redadd2(&out[((b * 128 + s) * 128 + t) * 2],
                r0.f.x + r0.f.y, r1.f.x + r1.f.y);
    }
}

// ---------------------------------------------------------------------------
extern "C" void kernel_launch(void* const* d_in, const int* in_sizes, int n_in,
                              void* d_out, int out_size)
{
    const float* a  = (const float*)d_in[0];   // (4,128,768)
    const float* bx = (const float*)d_in[1];   // (4,128,768)
    const float* W1 = (const float*)d_in[2];   // (1536,768)
    const float* b1 = (const float*)d_in[3];   // (768,)
    const float* W2 = (const float*)d_in[4];   // (768,2)
    const float* b2 = (const float*)d_in[5];   // (2,)
    float* out = (float*)d_out;                // (4,128,128,2)

    cvt_kernel<<<512, 256>>>(a, bx, W1, b2, out);
    gemm_kernel<<<dim3(8, 12, 2), 256>>>(b1);
    pair_kernel<<<dim3(4, 8, 32), 128>>>(W2, out);
}

// round 16
// speedup vs baseline: 1.0614x; 1.0614x over previous
#include <cuda_runtime.h>
#include <cuda_fp16.h>
#include <cstdint>

#define ULL unsigned long long

// ---------------- global scratch (no allocation) ----------------
__device__ float g_ha[512 * 768];
__device__ float g_hb[512 * 768];
__device__ __half g_xh[2][512 * 768];
__device__ __half g_wh[2][768 * 768];   // [k][n], natural layout

__device__ __forceinline__ ULL fma2(ULL a, ULL b, ULL c) {
    ULL d;
    asm("fma.rn.f32x2 %0, %1, %2, %3;" : "=l"(d) : "l"(a), "l"(b), "l"(c));
    return d;
}
__device__ __forceinline__ ULL add2(ULL a, ULL b) {
    ULL d;
    asm("add.rn.f32x2 %0, %1, %2;" : "=l"(d) : "l"(a), "l"(b));
    return d;
}
union F2U { ULL u; float2 f; };
union F4U { float4 f; ULL u[2]; float s[4]; uint4 q; };
union H4U { __half2 h2[2]; uint2 q; };

__device__ __forceinline__ uint32_t s2u(const void* p) {
    uint32_t a;
    asm("{ .reg .u64 t; cvta.to.shared.u64 t, %1; cvt.u32.u64 %0, t; }" : "=r"(a) : "l"(p));
    return a;
}
__device__ __forceinline__ void cpa16(const void* smem_dst, const void* gsrc) {
    uint32_t d = s2u(smem_dst);
    asm volatile("cp.async.ca.shared.global [%0], [%1], 16;" :: "r"(d), "l"(gsrc) : "memory");
}
__device__ __forceinline__ void redadd2(float* p, float v0, float v1) {
    asm volatile("red.global.add.v2.f32 [%0], {%1, %2};"
                 :: "l"(p), "f"(v0), "f"(v1) : "memory");
}
#define CP_COMMIT() asm volatile("cp.async.commit_group;" ::: "memory")
#define CP_WAIT2()  asm volatile("cp.async.wait_group 2;" ::: "memory")

#define LDSM4(r, addr)                                                         \
    asm volatile("ldmatrix.sync.aligned.m8n8.x4.shared.b16 {%0,%1,%2,%3}, [%4];" \
                 : "=r"((r)[0]), "=r"((r)[1]), "=r"((r)[2]), "=r"((r)[3])      \
                 : "r"(addr))
#define LDSM4T(r, addr)                                                        \
    asm volatile("ldmatrix.sync.aligned.m8n8.x4.trans.shared.b16 {%0,%1,%2,%3}, [%4];" \
                 : "=r"((r)[0]), "=r"((r)[1]), "=r"((r)[2]), "=r"((r)[3])      \
                 : "r"(addr))
#define MMA16816(c, a, b)                                                      \
    asm volatile("mma.sync.aligned.m16n8k16.row.col.f32.f16.f16.f32 "          \
                 "{%0,%1,%2,%3},{%4,%5,%6,%7},{%8,%9},{%0,%1,%2,%3};"          \
                 : "+f"((c)[0]), "+f"((c)[1]), "+f"((c)[2]), "+f"((c)[3])      \
                 : "r"((a)[0]), "r"((a)[1]), "r"((a)[2]), "r"((a)[3]),         \
                   "r"((b)[0]), "r"((b)[1]))

// ---------------------------------------------------------------------------
// cvt: fp32 -> fp16 for X and W1; init out=b2, g_ha=b1 (bcast), g_hb=0.
// R12's measured-best 2-unit-per-thread scheme, branch-free block ranges:
//   [0,384): X;  [384,960): W;  [960,1024): out-init;
//   [1024,1216): ha-init (b1);  [1216,1408): hb-init (0).
// ---------------------------------------------------------------------------
__global__ __launch_bounds__(256) void cvt_kernel(
    const float* __restrict__ A, const float* __restrict__ Bx,
    const float* __restrict__ W1, const float* __restrict__ b1,
    const float* __restrict__ b2, float* __restrict__ out)
{
    const int bid = blockIdx.x;
    const int tid = threadIdx.x;

    if (bid < 384) {
        const int u0 = (bid * 256 + tid) * 2;
        const int z  = u0 / 98304;
        const int r  = u0 - z * 98304;
        const float* src = (z ? Bx : A) + r * 4;
        float4 v0 = *(const float4*)(src);
        float4 v1 = *(const float4*)(src + 4);
        H4U h0, h1;
        h0.h2[0] = __float22half2_rn(make_float2(v0.x, v0.y));
        h0.h2[1] = __float22half2_rn(make_float2(v0.z, v0.w));
        h1.h2[0] = __float22half2_rn(make_float2(v1.x, v1.y));
        h1.h2[1] = __float22half2_rn(make_float2(v1.z, v1.w));
        uint4 q; q.x = h0.q.x; q.y = h0.q.y; q.z = h1.q.x; q.w = h1.q.y;
        *(uint4*)&g_xh[z][r * 4] = q;
    } else if (bid < 960) {
        const int u0 = ((bid - 384) * 256 + tid) * 2;
        const int z  = u0 / 147456;
        const int r  = u0 - z * 147456;
        const float* src = W1 + (z * 147456 + r) * 4;
        float4 v0 = *(const float4*)(src);
        float4 v1 = *(const float4*)(src + 4);
        H4U h0, h1;
        h0.h2[0] = __float22half2_rn(make_float2(v0.x, v0.y));
        h0.h2[1] = __float22half2_rn(make_float2(v0.z, v0.w));
        h1.h2[0] = __float22half2_rn(make_float2(v1.x, v1.y));
        h1.h2[1] = __float22half2_rn(make_float2(v1.z, v1.w));
        uint4 q; q.x = h0.q.x; q.y = h0.q.y; q.z = h1.q.x; q.w = h1.q.y;
        *(uint4*)&g_wh[z][r * 4] = q;
    } else if (bid < 1024) {
        const int i = ((bid - 960) * 256 + tid) * 2;
        const float b0 = b2[0], b1v = b2[1];
        const float4 r = make_float4(b0, b1v, b0, b1v);
        *(float4*)&out[i * 4]     = r;
        *(float4*)&out[i * 4 + 4] = r;
    } else if (bid < 1216) {
        const int i = ((bid - 1024) * 256 + tid) * 2;   // float4 unit
        float4 v0 = *(const float4*)&b1[(i % 192) * 4];
        float4 v1 = *(const float4*)&b1[((i + 1) % 192) * 4];
        *(float4*)&g_ha[i * 4]     = v0;
        *(float4*)&g_ha[i * 4 + 4] = v1;
    } else {
        const int i = ((bid - 1216) * 256 + tid) * 2;
        const float4 zr = make_float4(0.f, 0.f, 0.f, 0.f);
        *(float4*)&g_hb[i * 4]     = zr;
        *(float4*)&g_hb[i * 4 + 4] = zr;
    }
}

// ---------------------------------------------------------------------------
// gemm: fp16 warp-MMA GEMM, BM=128 / BN=64 / BK=32, K-SPLIT x2.
// W re-read 8x -> 4x: chip L2 traffic 36MB -> 27MB.  4-stage cp.async.
// Grid (4 m, 12 n, 4 = z*2+ks) = 192 CTAs, 256 thr (8 warps: 4m(32r) x 2n(32c)).
// Partials REDG'd onto g_ha/g_hb (pre-initialized to b1 / 0 by cvt).
// Dynamic smem: As[4][128][40] + Bs[4][32][72] halfs = 59392 B.
// ---------------------------------------------------------------------------
static constexpr int GEMM_SMEM = (4 * 128 * 40 + 4 * 32 * 72) * 2;  // 59392

__global__ __launch_bounds__(256) void gemm_kernel()
{
    extern __shared__ __align__(16) char dynsmem[];
    typedef __half AsT[128][40];
    typedef __half BsT[32][72];
    AsT* As = reinterpret_cast<AsT*>(dynsmem);                       // [4]
    BsT* Bs = reinterpret_cast<BsT*>(dynsmem + 4 * 128 * 40 * 2);    // [4]

    const int zz = blockIdx.z;
    const int z  = zz >> 1;
    const int c0 = (zz & 1) * 12;
    const int m0 = blockIdx.x * 128;
    const int n0 = blockIdx.y * 64;

    const int tid  = threadIdx.x;
    const int lane = tid & 31;
    const int wid  = tid >> 5;
    const int wm   = wid & 3;      // 32-row group
    const int wn   = wid >> 2;     // 32-col group

    const __half* __restrict__ xs = g_xh[z];
    const __half* __restrict__ ws = g_wh[z];

    float acc[2][4][4];            // [m-frag][n-frag(8col)][reg]
#pragma unroll
    for (int im = 0; im < 2; im++)
#pragma unroll
        for (int jn = 0; jn < 4; jn++)
#pragma unroll
            for (int r = 0; r < 4; r++) acc[im][jn][r] = 0.f;

    const int arow = (lane & 7) + 8 * ((lane >> 3) & 1);
    const int akh  = ((lane >> 4) & 1) * 8;
    const int bk   = (lane & 7) + 8 * ((lane >> 3) & 1);
    const int bn8  = ((lane >> 4) & 1) * 8;

    // A staging: 512 units (2/thread): u = tid + j*256 -> row u>>2, quad u&3
    // B staging: 256 units (1/thread): row tid>>3, quad tid&7
    const int bkr = tid >> 3, bq = tid & 7;

    auto issue = [&](int c, int s) {
        const int k0 = c * 32;
#pragma unroll
        for (int j = 0; j < 2; j++) {
            int u = tid + j * 256;
            int row = u >> 2, q = u & 3;
            cpa16(&As[s][row][q * 8], &xs[(m0 + row) * 768 + k0 + q * 8]);
        }
        cpa16(&Bs[s][bkr][bq * 8], &ws[(k0 + bkr) * 768 + n0 + bq * 8]);
    };

    issue(c0 + 0, 0); CP_COMMIT();
    issue(c0 + 1, 1); CP_COMMIT();
    issue(c0 + 2, 2); CP_COMMIT();

    for (int i = 0; i < 12; i++) {
        const int s = i & 3;
        CP_WAIT2();
        __syncthreads();

        if (i + 3 < 12) issue(c0 + i + 3, (i + 3) & 3);
        CP_COMMIT();

#pragma unroll
        for (int kk = 0; kk < 2; kk++) {
            uint32_t a_[2][4], b0_[4], b1_[4];
            LDSM4(a_[0], s2u(&As[s][wm * 32 + 0  + arow][kk * 16 + akh]));
            LDSM4(a_[1], s2u(&As[s][wm * 32 + 16 + arow][kk * 16 + akh]));
            LDSM4T(b0_, s2u(&Bs[s][kk * 16 + bk][wn * 32 + 0  + bn8]));
            LDSM4T(b1_, s2u(&Bs[s][kk * 16 + bk][wn * 32 + 16 + bn8]));
#pragma unroll
            for (int im = 0; im < 2; im++) {
                MMA16816(acc[im][0], a_[im], &b0_[0]);
                MMA16816(acc[im][1], a_[im], &b0_[2]);
                MMA16816(acc[im][2], a_[im], &b1_[0]);
                MMA16816(acc[im][3], a_[im], &b1_[2]);
            }
        }
    }

    // ---- epilogue: REDG partials onto pre-initialized g_ha/g_hb ----
    float* __restrict__ outp = z ? g_hb : g_ha;
#pragma unroll
    for (int im = 0; im < 2; im++)
#pragma unroll
        for (int jn = 0; jn < 4; jn++) {
            const int mA = m0 + wm * 32 + im * 16 + (lane >> 2);
            const int nG = n0 + wn * 32 + jn * 8 + 2 * (lane & 3);
            redadd2(&outp[mA * 768 + nG],       acc[im][jn][0], acc[im][jn][1]);
            redadd2(&outp[(mA + 8) * 768 + nG], acc[im][jn][2], acc[im][jn][3]);
        }
}

// ---------------------------------------------------------------------------
// pair_kernel (R15 v3 verbatim): 4 s per warp, h-split x8, single 96-h chunk.
// 1024 blocks x 4 warps = 27.7 warps/SM.  Grid (4 b, 8 s-tiles, 32 = hs*4+tt).
// Partials REDG'd (v2) onto out (pre-initialized to b2 by cvt).
// ---------------------------------------------------------------------------
__global__ __launch_bounds__(128) void pair_kernel(
    const float* __restrict__ W2, float* __restrict__ out)
{
    const int b  = blockIdx.x;
    const int s0 = blockIdx.y * 16;
    const int t0 = (blockIdx.z & 3) * 32;
    const int h0 = (blockIdx.z >> 2) * 96;

    __shared__ __align__(16) float4 haS[4][2][48];  // [w][s-pair][hp]
    __shared__ ULL hbT[48][33];                     // [hp][t]
    __shared__ __align__(16) float4 wsS[48];

    const int tid  = threadIdx.x;
    const int w    = tid >> 5;
    const int lane = tid & 31;

    unsigned aw[3], ap[3], ah[3];
#pragma unroll
    for (int i = 0; i < 3; i++) {
        unsigned q = (unsigned)tid + 128u * i;
        aw[i] = q / 96u;
        unsigned rem = q % 96u;
        ap[i] = rem / 48u;
        ah[i] = rem % 48u;
    }
    unsigned tq[6], hq[6];
#pragma unroll
    for (int i = 0; i < 6; i++) {
        unsigned q = (unsigned)tid + 128u * i;
        tq[i] = q / 24u; hq[i] = q % 24u;
    }

    float2 pa0[3], pa1[3];
    float4 pb[6];
    float4 pw;
#pragma unroll
    for (int i = 0; i < 3; i++) {
        int sa = b * 128 + s0 + 4 * aw[i] + 2 * ap[i];
        pa0[i] = *(const float2*)&g_ha[sa * 768 + h0 + 2 * ah[i]];
        pa1[i] = *(const float2*)&g_ha[(sa + 1) * 768 + h0 + 2 * ah[i]];
    }
#pragma unroll
    for (int i = 0; i < 6; i++)
        pb[i] = *(const float4*)&g_hb[(b * 128 + t0 + tq[i]) * 768 + h0 + hq[i] * 4];
    if (tid < 48) pw = *(const float4*)&W2[(h0 + 2 * tid) * 2];

#pragma unroll
    for (int i = 0; i < 3; i++)
        haS[aw[i]][ap[i]][ah[i]] = make_float4(pa0[i].x, pa0[i].y, pa1[i].x, pa1[i].y);
#pragma unroll
    for (int i = 0; i < 6; i++) {
        F2U d0; d0.f.x = pb[i].x; d0.f.y = pb[i].y;
        F2U d1; d1.f.x = pb[i].z; d1.f.y = pb[i].w;
        hbT[2 * hq[i] + 0][tq[i]] = d0.u;
        hbT[2 * hq[i] + 1][tq[i]] = d1.u;
    }
    if (tid < 48) wsS[tid] = make_float4(pw.x, pw.z, pw.y, pw.w);
    __syncthreads();

    ULL acc[4][2];
#pragma unroll
    for (int i = 0; i < 4; i++) { acc[i][0] = 0ull; acc[i][1] = 0ull; }

#pragma unroll 8
    for (int hp = 0; hp < 48; hp++) {
        F4U a0; a0.f = haS[w][0][hp];
        F4U a1; a1.f = haS[w][1][hp];
        ULL vb = hbT[hp][lane];
        F4U wv; wv.f = wsS[hp];

        F2U x00; x00.u = add2(a0.u[0], vb);
        x00.f.x = fmaxf(x00.f.x, 0.f); x00.f.y = fmaxf(x00.f.y, 0.f);
        F2U x01; x01.u = add2(a0.u[1], vb);
        x01.f.x = fmaxf(x01.f.x, 0.f); x01.f.y = fmaxf(x01.f.y, 0.f);
        F2U x10; x10.u = add2(a1.u[0], vb);
        x10.f.x = fmaxf(x10.f.x, 0.f); x10.f.y = fmaxf(x10.f.y, 0.f);
        F2U x11; x11.u = add2(a1.u[1], vb);
        x11.f.x = fmaxf(x11.f.x, 0.f); x11.f.y = fmaxf(x11.f.y, 0.f);

        acc[0][0] = fma2(x00.u, wv.u[0], acc[0][0]);
        acc[0][1] = fma2(x00.u, wv.u[1], acc[0][1]);
        acc[1][0] = fma2(x01.u, wv.u[0], acc[1][0]);
        acc[1][1] = fma2(x01.u, wv.u[1], acc[1][1]);
        acc[2][0] = fma2(x10.u, wv.u[0], acc[2][0]);
        acc[2][1] = fma2(x10.u, wv.u[1], acc[2][1]);
        acc[3][0] = fma2(x11.u, wv.u[0], acc[3][0]);
        acc[3][1] = fma2(x11.u, wv.u[1], acc[3][1]);
    }

    const int t = t0 + lane;
#pragma unroll
    for (int i = 0; i < 4; i++) {
        const int s = s0 + 4 * w + i;
        F2U r0, r1;
        r0.u = acc[i][0]; r1.u = acc[i][1];
        redadd2(&out[((b * 128 + s) * 128 + t) * 2],
                r0.f.x + r0.f.y, r1.f.x + r1.f.y);
    }
}

// ---------------------------------------------------------------------------
extern "C" void kernel_launch(void* const* d_in, const int* in_sizes, int n_in,
                              void* d_out, int out_size)
{
    const float* a  = (const float*)d_in[0];   // (4,128,768)
    const float* bx = (const float*)d_in[1];   // (4,128,768)
    const float* W1 = (const float*)d_in[2];   // (1536,768)
    const float* b1 = (const float*)d_in[3];   // (768,)
    const float* W2 = (const float*)d_in[4];   // (768,2)
    const float* b2 = (const float*)d_in[5];   // (2,)
    float* out = (float*)d_out;                // (4,128,128,2)

    cudaFuncSetAttribute(gemm_kernel,
                         cudaFuncAttributeMaxDynamicSharedMemorySize, GEMM_SMEM);

    cvt_kernel<<<1408, 256>>>(a, bx, W1, b1, b2, out);
    gemm_kernel<<<dim3(4, 12, 4), 256, GEMM_SMEM>>>();
    pair_kernel<<<dim3(4, 8, 32), 128>>>(W2, out);
}